// round 14
// baseline (speedup 1.0000x reference)
#include <cuda_runtime.h>
#include <cuda_fp16.h>
#include <cstdint>

#define N_NODES 15279
#define M_PAD   15360
#define E_EDGES 488928
#define IN_CH   1024
#define N_HID   512
#define N_CLASS 16
#define EMB_DIM 128

// ---------------- scratch (static device memory; no allocations) -------------
__device__ __half g_a[(size_t)M_PAD * IN_CH];            // 31.5 MB fp16 activations (pad rows stay 0)
__device__ __half g_b[(size_t)N_HID * IN_CH];            // 1 MB  (W1^T fp16)
__device__ __half g_t1[(size_t)N_NODES * N_HID];         // 15.7 MB h0@W1 (fp16)
__device__ float g_t2[(size_t)N_NODES * N_CLASS];        //  1.0 MB fused spmm1+gemm2 out
__device__ int   g_counts[N_NODES];                      // zero at load; re-zeroed by scan
__device__ int   g_rowptr[N_NODES + 1];
__device__ int   g_cursor[N_NODES];
__device__ int   g_ecol[E_EDGES];
__device__ float g_eval[E_EDGES];

// ---------------- PTX helpers (sm_80+ features only) -------------------------
static __device__ __forceinline__ uint32_t s2u(const void* p) {
    uint32_t a;
    asm("{ .reg .u64 t; cvta.to.shared.u64 t, %1; cvt.u32.u64 %0, t; }" : "=r"(a) : "l"(p));
    return a;
}
static __device__ __forceinline__ void cp16(uint32_t dst, const void* src) {
    asm volatile("cp.async.cg.shared.global [%0], [%1], 16;" :: "r"(dst), "l"(src));
}
static __device__ __forceinline__ void cp_commit() {
    asm volatile("cp.async.commit_group;" ::: "memory");
}
static __device__ __forceinline__ void cp_wait2() {
    asm volatile("cp.async.wait_group 2;" ::: "memory");
}
static __device__ __forceinline__ void ldsm4(uint32_t* r, uint32_t a) {
    asm volatile("ldmatrix.sync.aligned.m8n8.x4.shared.b16 {%0,%1,%2,%3}, [%4];"
                 : "=r"(r[0]), "=r"(r[1]), "=r"(r[2]), "=r"(r[3]) : "r"(a));
}
static __device__ __forceinline__ void mma16816f16(float* d, const uint32_t* a, const uint32_t* b) {
    asm volatile(
        "mma.sync.aligned.m16n8k16.row.col.f32.f16.f16.f32 "
        "{%0,%1,%2,%3}, {%4,%5,%6,%7}, {%8,%9}, {%0,%1,%2,%3};"
        : "+f"(d[0]), "+f"(d[1]), "+f"(d[2]), "+f"(d[3])
        : "r"(a[0]), "r"(a[1]), "r"(a[2]), "r"(a[3]), "r"(b[0]), "r"(b[1]));
}

// ---------------- embedding lookup + relu -> fp16 (2 nodes/block, MLP=2) -----
// Dtype detection via the GLOBAL first 16 int32 words of x (in-bounds under
// both interpretations): int64 x has all odd (high) words zero; int32 x has
// 8 uniform [0,10000) indices there (all-zero prob ~1e-32).
__global__ void embed_kernel(const int* __restrict__ x32, const float* __restrict__ emb) {
    int g = blockIdx.x;
    int w = threadIdx.x >> 5, lane = threadIdx.x & 31;
    int j = lane & 15;
    int probe = __ldg(x32 + j);
    unsigned nz = __ballot_sync(0xFFFFFFFFu, (j & 1) && probe != 0);
    bool is64 = (nz == 0);
    int n0 = 2 * g, n1 = 2 * g + 1;
    bool v1 = (n1 < N_NODES);
    int idx0 = is64 ? __ldg(x32 + 2 * (n0 * 8 + w)) : __ldg(x32 + n0 * 8 + w);
    int idx1 = 0;
    if (v1) idx1 = is64 ? __ldg(x32 + 2 * (n1 * 8 + w)) : __ldg(x32 + n1 * 8 + w);
    // two independent gathers in flight
    float4 a0 = __ldg((const float4*)(emb + (size_t)idx0 * EMB_DIM) + lane);
    float4 a1 = make_float4(0.f, 0.f, 0.f, 0.f);
    if (v1) a1 = __ldg((const float4*)(emb + (size_t)idx1 * EMB_DIM) + lane);
    __half h0[4], h1[4];
    h0[0] = __float2half(fmaxf(a0.x, 0.f)); h0[1] = __float2half(fmaxf(a0.y, 0.f));
    h0[2] = __float2half(fmaxf(a0.z, 0.f)); h0[3] = __float2half(fmaxf(a0.w, 0.f));
    h1[0] = __float2half(fmaxf(a1.x, 0.f)); h1[1] = __float2half(fmaxf(a1.y, 0.f));
    h1[2] = __float2half(fmaxf(a1.z, 0.f)); h1[3] = __float2half(fmaxf(a1.w, 0.f));
    size_t off0 = (size_t)n0 * IN_CH + w * EMB_DIM + lane * 4;
    *(uint2*)(g_a + off0) = *(uint2*)h0;
    if (v1) {
        size_t off1 = (size_t)n1 * IN_CH + w * EMB_DIM + lane * 4;
        *(uint2*)(g_a + off1) = *(uint2*)h1;
    }
}

// W1 [K=1024, N=512] fp32 -> B [N=512, K=1024] fp16 (transposed)
__global__ void convw1_kernel(const float* __restrict__ W1) {
    int i = blockIdx.x * blockDim.x + threadIdx.x;
    if (i >= N_HID * IN_CH / 2) return;
    int n = i / (IN_CH / 2);
    int k2 = (i % (IN_CH / 2)) * 2;
    float v0 = __ldg(W1 + (size_t)k2 * N_HID + n);
    float v1 = __ldg(W1 + (size_t)(k2 + 1) * N_HID + n);
    __half ph[2] = {__float2half(v0), __float2half(v1)};
    *(uint32_t*)(g_b + (size_t)n * IN_CH + k2) = *(uint32_t*)ph;
}

// ---------------- GEMM1 via mma.sync fp16: t1 = A @ B^T ----------------------
// block tile 128x128, BK=64, 8 warps (4Mx2N), warp tile 32x64,
// SW128-swizzled smem rows (128B), 3-stage cp.async pipeline, 2 CTAs/SM.
#define BKC 64
#define AT  16384                      // 128 rows x 64 fp16 x 2B
#define BT  16384                      // 128 rows x 64 fp16 x 2B
#define SSIZE (AT + BT)                // 32768
#define NSTAGE 3
#define GEMM_SMEM (NSTAGE * SSIZE)     // 98304

static __device__ __forceinline__ void gissue(uint32_t sb, int s, int k0,
                                              int bm, int bn, int tid) {
    if (k0 < IN_CH) {
        uint32_t stage = sb + s * SSIZE;
#pragma unroll
        for (int l = 0; l < 4; l++) {
            int unit = tid + l * 256;
            int r = unit >> 3, u = unit & 7;
            uint32_t bo = (r << 7) | (u << 4);
            uint32_t sw = bo ^ ((bo >> 3) & 0x70);
            cp16(stage + sw, g_a + (size_t)(bm + r) * IN_CH + k0 + u * 8);
            cp16(stage + AT + sw, g_b + (size_t)(bn + r) * IN_CH + k0 + u * 8);
        }
    }
    cp_commit();
}

__global__ void __launch_bounds__(256, 2) gemm1_mma_kernel() {
    extern __shared__ char smem[];
    uint32_t sb = s2u(smem);
    const int tid = threadIdx.x;
    const int wid = tid >> 5, lane = tid & 31;
    const int bm = blockIdx.y * 128, bn = blockIdx.x * 128;
    const int warp_m = (wid & 3) * 32;
    const int warp_n = (wid >> 2) * 64;

    uint32_t a_off[2], b_off[4];
#pragma unroll
    for (int mi = 0; mi < 2; mi++) {
        int row = warp_m + mi * 16 + ((lane >> 3) & 1) * 8 + (lane & 7);
        a_off[mi] = (uint32_t)((row << 7) | ((lane >> 4) << 4));
    }
#pragma unroll
    for (int p = 0; p < 4; p++) {
        int row = warp_n + p * 16 + (lane >> 4) * 8 + (lane & 7);
        b_off[p] = (uint32_t)((row << 7) | (((lane >> 3) & 1) << 4));
    }

    float acc[2][8][4];
#pragma unroll
    for (int mi = 0; mi < 2; mi++)
#pragma unroll
        for (int nj = 0; nj < 8; nj++)
#pragma unroll
            for (int q = 0; q < 4; q++) acc[mi][nj][q] = 0.f;

    gissue(sb, 0, 0, bm, bn, tid);
    gissue(sb, 1, BKC, bm, bn, tid);
    gissue(sb, 2, 2 * BKC, bm, bn, tid);

    const int NCHUNK = IN_CH / BKC;   // 16
    int stage_id = 0;
    for (int c = 0; c < NCHUNK; c++) {
        cp_wait2();
        __syncthreads();
        uint32_t stage = sb + stage_id * SSIZE;
#pragma unroll
        for (int kk = 0; kk < 4; kk++) {
            uint32_t ubase = (uint32_t)(kk * 2) << 4;
            uint32_t af[2][4];
#pragma unroll
            for (int mi = 0; mi < 2; mi++) {
                uint32_t bo = a_off[mi] + ubase;
                ldsm4(af[mi], stage + (bo ^ ((bo >> 3) & 0x70)));
            }
            uint32_t bf[8][2];
#pragma unroll
            for (int p = 0; p < 4; p++) {
                uint32_t bo = b_off[p] + ubase;
                uint32_t t[4];
                ldsm4(t, stage + AT + (bo ^ ((bo >> 3) & 0x70)));
                bf[2 * p][0] = t[0]; bf[2 * p][1] = t[1];
                bf[2 * p + 1][0] = t[2]; bf[2 * p + 1][1] = t[3];
            }
#pragma unroll
            for (int mi = 0; mi < 2; mi++)
#pragma unroll
                for (int nj = 0; nj < 8; nj++)
                    mma16816f16(acc[mi][nj], af[mi], bf[nj]);
        }
        __syncthreads();
        gissue(sb, stage_id, (c + NSTAGE) * BKC, bm, bn, tid);
        stage_id = (stage_id == NSTAGE - 1) ? 0 : stage_id + 1;
    }

    // epilogue -> fp16 t1
#pragma unroll
    for (int mi = 0; mi < 2; mi++) {
        int r0 = bm + warp_m + mi * 16 + (lane >> 2);
        int r1 = r0 + 8;
#pragma unroll
        for (int nj = 0; nj < 8; nj++) {
            int col = bn + warp_n + nj * 8 + (lane & 3) * 2;
            if (r0 < N_NODES)
                *(__half2*)(g_t1 + (size_t)r0 * N_HID + col) =
                    __floats2half2_rn(acc[mi][nj][0], acc[mi][nj][1]);
            if (r1 < N_NODES)
                *(__half2*)(g_t1 + (size_t)r1 * N_HID + col) =
                    __floats2half2_rn(acc[mi][nj][2], acc[mi][nj][3]);
        }
    }
}

// ---------------- CSR build --------------------------------------------------
__global__ void hist_kernel(const int* __restrict__ rows, int E) {
    int i = blockIdx.x * blockDim.x + threadIdx.x;
    if (i < E) atomicAdd(&g_counts[rows[i]], 1);
}

// thread-coarsened shuffle scan; zeroes g_counts and seeds g_cursor
#define SCAN_PER 15
__global__ void __launch_bounds__(1024) scan_kernel() {
    __shared__ int wsum[32];
    int tid = threadIdx.x;
    int lane = tid & 31, w = tid >> 5;
    int base = tid * SCAN_PER;
    int c[SCAN_PER];
    int sum = 0;
#pragma unroll
    for (int i = 0; i < SCAN_PER; i++) {
        int g = base + i;
        c[i] = (g < N_NODES) ? g_counts[g] : 0;
        if (g < N_NODES) g_counts[g] = 0;
        sum += c[i];
    }
    int incl = sum;
#pragma unroll
    for (int off = 1; off < 32; off <<= 1) {
        int t = __shfl_up_sync(0xFFFFFFFFu, incl, off);
        if (lane >= off) incl += t;
    }
    if (lane == 31) wsum[w] = incl;
    __syncthreads();
    if (w == 0) {
        int v = wsum[lane];
#pragma unroll
        for (int off = 1; off < 32; off <<= 1) {
            int t = __shfl_up_sync(0xFFFFFFFFu, v, off);
            if (lane >= off) v += t;
        }
        wsum[lane] = v;
    }
    __syncthreads();
    int run = (w > 0 ? wsum[w - 1] : 0) + incl - sum;   // exclusive prefix
    if (tid == 0) g_rowptr[0] = 0;
#pragma unroll
    for (int i = 0; i < SCAN_PER; i++) {
        int g = base + i;
        if (g < N_NODES) {
            g_cursor[g] = run;
            run += c[i];
            g_rowptr[g + 1] = run;
        }
    }
}

__global__ void scatter_kernel(const int* __restrict__ rows, const int* __restrict__ cols,
                               const float* __restrict__ vals, int E) {
    int i = blockIdx.x * blockDim.x + threadIdx.x;
    if (i < E) {
        int r = rows[i];
        int p = atomicAdd(&g_cursor[r], 1);
        g_ecol[p] = cols[i];
        g_eval[p] = vals[i];
    }
}

// ---------------- fused SpMM1+GEMM2: t2 = (relu(A@t1 + b1)) @ W2 -------------
// 8 rows per 128-thread block. Per row: CSR gather into fp32 h (128 threads x
// 4 channels), then in-block h @ W2 via smem-staged fp16 W2^T + shfl reduction.
// h never touches global memory (stays fp32 -> better accuracy than fp16 h1).
#define ROWS_PB 8
__global__ __launch_bounds__(128) void spmm1_fused_kernel(const float* __restrict__ b1,
                                                          const float* __restrict__ W2) {
    __shared__ __half Ws[N_CLASS * N_HID];   // W2^T, fp16: Ws[c*512 + k]
    __shared__ float red[4][N_CLASS];
    int tid = threadIdx.x;
    int w = tid >> 5, lane = tid & 31;

    // stage W2^T (fp16): 8192 elements, 64 per thread
    for (int i = tid; i < N_CLASS * N_HID; i += 128) {
        int c = i >> 9, k = i & 511;
        Ws[i] = __float2half(__ldg(W2 + (size_t)k * N_CLASS + c));
    }
    float4 bb = __ldg((const float4*)b1 + tid);
    __syncthreads();

    const uint2* Ws2 = (const uint2*)Ws;   // 4 halves per uint2; [c*128 + tid]

    for (int rr = 0; rr < ROWS_PB; rr++) {
        int r = blockIdx.x * ROWS_PB + rr;
        bool valid = (r < N_NODES);
        float hx = 0.f, hy = 0.f, hz = 0.f, hw = 0.f;
        if (valid) {
            int s = g_rowptr[r], e = g_rowptr[r + 1];
            float4 acc0 = make_float4(0.f, 0.f, 0.f, 0.f);
            float4 acc1 = make_float4(0.f, 0.f, 0.f, 0.f);
            int i = s;
            for (; i + 1 < e; i += 2) {
                int   c0 = g_ecol[i],     c1 = g_ecol[i + 1];
                float v0 = g_eval[i],     v1 = g_eval[i + 1];
                uint2 r0 = __ldg((const uint2*)(g_t1 + (size_t)c0 * N_HID) + tid);
                uint2 r1 = __ldg((const uint2*)(g_t1 + (size_t)c1 * N_HID) + tid);
                float2 p0 = __half22float2(*(__half2*)&r0.x), p1 = __half22float2(*(__half2*)&r0.y);
                float2 q0 = __half22float2(*(__half2*)&r1.x), q1 = __half22float2(*(__half2*)&r1.y);
                acc0.x += v0 * p0.x; acc0.y += v0 * p0.y; acc0.z += v0 * p1.x; acc0.w += v0 * p1.y;
                acc1.x += v1 * q0.x; acc1.y += v1 * q0.y; acc1.z += v1 * q1.x; acc1.w += v1 * q1.y;
            }
            if (i < e) {
                int   c = g_ecol[i];
                float v = g_eval[i];
                uint2 r0 = __ldg((const uint2*)(g_t1 + (size_t)c * N_HID) + tid);
                float2 p0 = __half22float2(*(__half2*)&r0.x), p1 = __half22float2(*(__half2*)&r0.y);
                acc0.x += v * p0.x; acc0.y += v * p0.y; acc0.z += v * p1.x; acc0.w += v * p1.y;
            }
            hx = fmaxf(acc0.x + acc1.x + bb.x, 0.f);
            hy = fmaxf(acc0.y + acc1.y + bb.y, 0.f);
            hz = fmaxf(acc0.z + acc1.z + bb.z, 0.f);
            hw = fmaxf(acc0.w + acc1.w + bb.w, 0.f);
        }
        // per-thread partial t2[c] over its 4 k-channels
        float p[N_CLASS];
#pragma unroll
        for (int c = 0; c < N_CLASS; c++) {
            uint2 ww = Ws2[c * 128 + tid];
            float2 w0 = __half22float2(*(__half2*)&ww.x);
            float2 w1 = __half22float2(*(__half2*)&ww.y);
            p[c] = hx * w0.x + hy * w0.y + hz * w1.x + hw * w1.y;
        }
        // warp reduce all 16
#pragma unroll
        for (int c = 0; c < N_CLASS; c++) {
            p[c] += __shfl_down_sync(0xFFFFFFFFu, p[c], 16);
            p[c] += __shfl_down_sync(0xFFFFFFFFu, p[c], 8);
            p[c] += __shfl_down_sync(0xFFFFFFFFu, p[c], 4);
            p[c] += __shfl_down_sync(0xFFFFFFFFu, p[c], 2);
            p[c] += __shfl_down_sync(0xFFFFFFFFu, p[c], 1);
        }
        if (lane == 0) {
#pragma unroll
            for (int c = 0; c < N_CLASS; c++) red[w][c] = p[c];
        }
        __syncthreads();
        if (tid < N_CLASS && valid)
            g_t2[(size_t)r * N_CLASS + tid] =
                red[0][tid] + red[1][tid] + red[2][tid] + red[3][tid];
        __syncthreads();
    }
}

// ---------------- SpMM2 (+b2): out = A @ g_t2 + b2 ---------------------------
__global__ void spmm2_kernel(const float* __restrict__ b2, float* __restrict__ out) {
    int w = (blockIdx.x * blockDim.x + threadIdx.x) >> 5;
    int lane = threadIdx.x & 31;
    if (w >= N_NODES) return;
    int s = g_rowptr[w], e = g_rowptr[w + 1];
    float acc = 0.f;
    for (int i = s; i < e; i++) {
        int   c = g_ecol[i];
        float v = g_eval[i];
        if (lane < N_CLASS) acc += v * __ldg(g_t2 + (size_t)c * N_CLASS + lane);
    }
    if (lane < N_CLASS) out[(size_t)w * N_CLASS + lane] = acc + b2[lane];
}

// ---------------- launch: dual-stream DAG ------------------------------------
extern "C" void kernel_launch(void* const* d_in, const int* in_sizes, int n_in,
                              void* d_out, int out_size) {
    const int*   x    = (const int*)d_in[0];
    const int*   rows = (const int*)d_in[1];
    const int*   cols = (const int*)d_in[2];
    const float* vals = (const float*)d_in[3];
    const float* emb  = (const float*)d_in[4];
    const float* W1   = (const float*)d_in[5];
    const float* b1   = (const float*)d_in[6];
    const float* W2   = (const float*)d_in[7];
    const float* b2   = (const float*)d_in[8];
    float* out = (float*)d_out;
    int E = in_sizes[1];

    static cudaStream_t s_side = nullptr;
    static cudaEvent_t  ev_fork = nullptr, ev_w1 = nullptr, ev_join = nullptr;
    if (s_side == nullptr) {
        cudaStreamCreateWithFlags(&s_side, cudaStreamNonBlocking);
        cudaEventCreateWithFlags(&ev_fork, cudaEventDisableTiming);
        cudaEventCreateWithFlags(&ev_w1, cudaEventDisableTiming);
        cudaEventCreateWithFlags(&ev_join, cudaEventDisableTiming);
    }

    cudaFuncSetAttribute(gemm1_mma_kernel,
                         cudaFuncAttributeMaxDynamicSharedMemorySize, GEMM_SMEM);

    // fork: weight-convert + CSR chain on side stream; embed/GEMM on main
    cudaEventRecord(ev_fork, 0);
    cudaStreamWaitEvent(s_side, ev_fork, 0);

    convw1_kernel<<<(N_HID * IN_CH / 2 + 255) / 256, 256, 0, s_side>>>(W1);
    cudaEventRecord(ev_w1, s_side);
    hist_kernel<<<(E + 255) / 256, 256, 0, s_side>>>(rows, E);
    scan_kernel<<<1, 1024, 0, s_side>>>();
    scatter_kernel<<<(E + 255) / 256, 256, 0, s_side>>>(rows, cols, vals, E);
    cudaEventRecord(ev_join, s_side);

    embed_kernel<<<(N_NODES + 1) / 2, 256>>>(x, emb);
    cudaStreamWaitEvent(0, ev_w1, 0);   // gemm1 needs converted W1
    gemm1_mma_kernel<<<dim3(N_HID / 128, M_PAD / 128), 256, GEMM_SMEM>>>();

    cudaStreamWaitEvent(0, ev_join, 0); // sparse kernels need the CSR
    spmm1_fused_kernel<<<(N_NODES + ROWS_PB - 1) / ROWS_PB, 128>>>(b1, W2);
    spmm2_kernel<<<(N_NODES * 32 + 255) / 256, 256>>>(b2, out);
}

// round 16
// speedup vs baseline: 1.3158x; 1.3158x over previous
#include <cuda_runtime.h>
#include <cuda_fp16.h>
#include <cstdint>

#define N_NODES 15279
#define M_PAD   15360
#define E_EDGES 488928
#define IN_CH   1024
#define N_HID   512
#define N_CLASS 16
#define EMB_DIM 128

// ---------------- scratch (static device memory; no allocations) -------------
__device__ __half g_a[(size_t)M_PAD * IN_CH];            // 31.5 MB fp16 activations (pad rows stay 0)
__device__ __half g_b[(size_t)N_HID * IN_CH];            // 1 MB  (W1^T fp16)
__device__ __half g_t1[(size_t)N_NODES * N_HID];         // 15.7 MB h0@W1 (fp16)
__device__ __half g_h1[(size_t)N_NODES * N_HID];         // 15.7 MB relu(spmm+b1) (fp16)
__device__ float g_t2[(size_t)N_NODES * N_CLASS];        //  1.0 MB h1@W2
__device__ int   g_counts[N_NODES];                      // zero at load; re-zeroed by scan
__device__ int   g_rowptr[N_NODES + 1];
__device__ int   g_cursor[N_NODES];
__device__ int   g_ecol[E_EDGES];
__device__ float g_eval[E_EDGES];

// ---------------- PTX helpers (sm_80+ features only) -------------------------
static __device__ __forceinline__ uint32_t s2u(const void* p) {
    uint32_t a;
    asm("{ .reg .u64 t; cvta.to.shared.u64 t, %1; cvt.u32.u64 %0, t; }" : "=r"(a) : "l"(p));
    return a;
}
static __device__ __forceinline__ void cp16(uint32_t dst, const void* src) {
    asm volatile("cp.async.cg.shared.global [%0], [%1], 16;" :: "r"(dst), "l"(src));
}
static __device__ __forceinline__ void cp_commit() {
    asm volatile("cp.async.commit_group;" ::: "memory");
}
static __device__ __forceinline__ void cp_wait2() {
    asm volatile("cp.async.wait_group 2;" ::: "memory");
}
static __device__ __forceinline__ void ldsm4(uint32_t* r, uint32_t a) {
    asm volatile("ldmatrix.sync.aligned.m8n8.x4.shared.b16 {%0,%1,%2,%3}, [%4];"
                 : "=r"(r[0]), "=r"(r[1]), "=r"(r[2]), "=r"(r[3]) : "r"(a));
}
static __device__ __forceinline__ void mma16816f16(float* d, const uint32_t* a, const uint32_t* b) {
    asm volatile(
        "mma.sync.aligned.m16n8k16.row.col.f32.f16.f16.f32 "
        "{%0,%1,%2,%3}, {%4,%5,%6,%7}, {%8,%9}, {%0,%1,%2,%3};"
        : "+f"(d[0]), "+f"(d[1]), "+f"(d[2]), "+f"(d[3])
        : "r"(a[0]), "r"(a[1]), "r"(a[2]), "r"(a[3]), "r"(b[0]), "r"(b[1]));
}

// ---------------- embedding lookup + relu -> fp16 (2 nodes/block, MLP=2) -----
// Dtype detection via the GLOBAL first 16 int32 words of x (in-bounds under
// both interpretations): int64 x has all odd (high) words zero; int32 x has
// 8 uniform [0,10000) indices there (all-zero prob ~1e-32).
__global__ void embed_kernel(const int* __restrict__ x32, const float* __restrict__ emb) {
    int g = blockIdx.x;
    int w = threadIdx.x >> 5, lane = threadIdx.x & 31;
    int j = lane & 15;
    int probe = __ldg(x32 + j);
    unsigned nz = __ballot_sync(0xFFFFFFFFu, (j & 1) && probe != 0);
    bool is64 = (nz == 0);
    int n0 = 2 * g, n1 = 2 * g + 1;
    bool v1 = (n1 < N_NODES);
    int idx0 = is64 ? __ldg(x32 + 2 * (n0 * 8 + w)) : __ldg(x32 + n0 * 8 + w);
    int idx1 = 0;
    if (v1) idx1 = is64 ? __ldg(x32 + 2 * (n1 * 8 + w)) : __ldg(x32 + n1 * 8 + w);
    float4 a0 = __ldg((const float4*)(emb + (size_t)idx0 * EMB_DIM) + lane);
    float4 a1 = make_float4(0.f, 0.f, 0.f, 0.f);
    if (v1) a1 = __ldg((const float4*)(emb + (size_t)idx1 * EMB_DIM) + lane);
    __half h0[4], h1[4];
    h0[0] = __float2half(fmaxf(a0.x, 0.f)); h0[1] = __float2half(fmaxf(a0.y, 0.f));
    h0[2] = __float2half(fmaxf(a0.z, 0.f)); h0[3] = __float2half(fmaxf(a0.w, 0.f));
    h1[0] = __float2half(fmaxf(a1.x, 0.f)); h1[1] = __float2half(fmaxf(a1.y, 0.f));
    h1[2] = __float2half(fmaxf(a1.z, 0.f)); h1[3] = __float2half(fmaxf(a1.w, 0.f));
    size_t off0 = (size_t)n0 * IN_CH + w * EMB_DIM + lane * 4;
    *(uint2*)(g_a + off0) = *(uint2*)h0;
    if (v1) {
        size_t off1 = (size_t)n1 * IN_CH + w * EMB_DIM + lane * 4;
        *(uint2*)(g_a + off1) = *(uint2*)h1;
    }
}

// W1 [K=1024, N=512] fp32 -> B [N=512, K=1024] fp16 (transposed)
__global__ void convw1_kernel(const float* __restrict__ W1) {
    int i = blockIdx.x * blockDim.x + threadIdx.x;
    if (i >= N_HID * IN_CH / 2) return;
    int n = i / (IN_CH / 2);
    int k2 = (i % (IN_CH / 2)) * 2;
    float v0 = __ldg(W1 + (size_t)k2 * N_HID + n);
    float v1 = __ldg(W1 + (size_t)(k2 + 1) * N_HID + n);
    __half ph[2] = {__float2half(v0), __float2half(v1)};
    *(uint32_t*)(g_b + (size_t)n * IN_CH + k2) = *(uint32_t*)ph;
}

// ---------------- GEMM1 via mma.sync fp16: t1 = A @ B^T ----------------------
// block tile 128x128, BK=64, 8 warps (4Mx2N), warp tile 32x64,
// SW128-swizzled smem rows (128B), 3-stage cp.async pipeline, 2 CTAs/SM.
#define BKC 64
#define AT  16384                      // 128 rows x 64 fp16 x 2B
#define BT  16384                      // 128 rows x 64 fp16 x 2B
#define SSIZE (AT + BT)                // 32768
#define NSTAGE 3
#define GEMM_SMEM (NSTAGE * SSIZE)     // 98304

static __device__ __forceinline__ void gissue(uint32_t sb, int s, int k0,
                                              int bm, int bn, int tid) {
    if (k0 < IN_CH) {
        uint32_t stage = sb + s * SSIZE;
#pragma unroll
        for (int l = 0; l < 4; l++) {
            int unit = tid + l * 256;
            int r = unit >> 3, u = unit & 7;
            uint32_t bo = (r << 7) | (u << 4);
            uint32_t sw = bo ^ ((bo >> 3) & 0x70);
            cp16(stage + sw, g_a + (size_t)(bm + r) * IN_CH + k0 + u * 8);
            cp16(stage + AT + sw, g_b + (size_t)(bn + r) * IN_CH + k0 + u * 8);
        }
    }
    cp_commit();
}

__global__ void __launch_bounds__(256, 2) gemm1_mma_kernel() {
    extern __shared__ char smem[];
    uint32_t sb = s2u(smem);
    const int tid = threadIdx.x;
    const int wid = tid >> 5, lane = tid & 31;
    const int bm = blockIdx.y * 128, bn = blockIdx.x * 128;
    const int warp_m = (wid & 3) * 32;
    const int warp_n = (wid >> 2) * 64;

    uint32_t a_off[2], b_off[4];
#pragma unroll
    for (int mi = 0; mi < 2; mi++) {
        int row = warp_m + mi * 16 + ((lane >> 3) & 1) * 8 + (lane & 7);
        a_off[mi] = (uint32_t)((row << 7) | ((lane >> 4) << 4));
    }
#pragma unroll
    for (int p = 0; p < 4; p++) {
        int row = warp_n + p * 16 + (lane >> 4) * 8 + (lane & 7);
        b_off[p] = (uint32_t)((row << 7) | (((lane >> 3) & 1) << 4));
    }

    float acc[2][8][4];
#pragma unroll
    for (int mi = 0; mi < 2; mi++)
#pragma unroll
        for (int nj = 0; nj < 8; nj++)
#pragma unroll
            for (int q = 0; q < 4; q++) acc[mi][nj][q] = 0.f;

    gissue(sb, 0, 0, bm, bn, tid);
    gissue(sb, 1, BKC, bm, bn, tid);
    gissue(sb, 2, 2 * BKC, bm, bn, tid);

    const int NCHUNK = IN_CH / BKC;   // 16
    int stage_id = 0;
    for (int c = 0; c < NCHUNK; c++) {
        cp_wait2();
        __syncthreads();
        uint32_t stage = sb + stage_id * SSIZE;
#pragma unroll
        for (int kk = 0; kk < 4; kk++) {
            uint32_t ubase = (uint32_t)(kk * 2) << 4;
            uint32_t af[2][4];
#pragma unroll
            for (int mi = 0; mi < 2; mi++) {
                uint32_t bo = a_off[mi] + ubase;
                ldsm4(af[mi], stage + (bo ^ ((bo >> 3) & 0x70)));
            }
            uint32_t bf[8][2];
#pragma unroll
            for (int p = 0; p < 4; p++) {
                uint32_t bo = b_off[p] + ubase;
                uint32_t t[4];
                ldsm4(t, stage + AT + (bo ^ ((bo >> 3) & 0x70)));
                bf[2 * p][0] = t[0]; bf[2 * p][1] = t[1];
                bf[2 * p + 1][0] = t[2]; bf[2 * p + 1][1] = t[3];
            }
#pragma unroll
            for (int mi = 0; mi < 2; mi++)
#pragma unroll
                for (int nj = 0; nj < 8; nj++)
                    mma16816f16(acc[mi][nj], af[mi], bf[nj]);
        }
        __syncthreads();
        gissue(sb, stage_id, (c + NSTAGE) * BKC, bm, bn, tid);
        stage_id = (stage_id == NSTAGE - 1) ? 0 : stage_id + 1;
    }

    // epilogue -> fp16 t1
#pragma unroll
    for (int mi = 0; mi < 2; mi++) {
        int r0 = bm + warp_m + mi * 16 + (lane >> 2);
        int r1 = r0 + 8;
#pragma unroll
        for (int nj = 0; nj < 8; nj++) {
            int col = bn + warp_n + nj * 8 + (lane & 3) * 2;
            if (r0 < N_NODES)
                *(__half2*)(g_t1 + (size_t)r0 * N_HID + col) =
                    __floats2half2_rn(acc[mi][nj][0], acc[mi][nj][1]);
            if (r1 < N_NODES)
                *(__half2*)(g_t1 + (size_t)r1 * N_HID + col) =
                    __floats2half2_rn(acc[mi][nj][2], acc[mi][nj][3]);
        }
    }
}

// ---------------- CSR build --------------------------------------------------
__global__ void hist_kernel(const int* __restrict__ rows, int E) {
    int i = blockIdx.x * blockDim.x + threadIdx.x;
    if (i < E) atomicAdd(&g_counts[rows[i]], 1);
}

// thread-coarsened shuffle scan; zeroes g_counts and seeds g_cursor
#define SCAN_PER 15
__global__ void __launch_bounds__(1024) scan_kernel() {
    __shared__ int wsum[32];
    int tid = threadIdx.x;
    int lane = tid & 31, w = tid >> 5;
    int base = tid * SCAN_PER;
    int c[SCAN_PER];
    int sum = 0;
#pragma unroll
    for (int i = 0; i < SCAN_PER; i++) {
        int g = base + i;
        c[i] = (g < N_NODES) ? g_counts[g] : 0;
        if (g < N_NODES) g_counts[g] = 0;
        sum += c[i];
    }
    int incl = sum;
#pragma unroll
    for (int off = 1; off < 32; off <<= 1) {
        int t = __shfl_up_sync(0xFFFFFFFFu, incl, off);
        if (lane >= off) incl += t;
    }
    if (lane == 31) wsum[w] = incl;
    __syncthreads();
    if (w == 0) {
        int v = wsum[lane];
#pragma unroll
        for (int off = 1; off < 32; off <<= 1) {
            int t = __shfl_up_sync(0xFFFFFFFFu, v, off);
            if (lane >= off) v += t;
        }
        wsum[lane] = v;
    }
    __syncthreads();
    int run = (w > 0 ? wsum[w - 1] : 0) + incl - sum;   // exclusive prefix
    if (tid == 0) g_rowptr[0] = 0;
#pragma unroll
    for (int i = 0; i < SCAN_PER; i++) {
        int g = base + i;
        if (g < N_NODES) {
            g_cursor[g] = run;
            run += c[i];
            g_rowptr[g + 1] = run;
        }
    }
}

__global__ void scatter_kernel(const int* __restrict__ rows, const int* __restrict__ cols,
                               const float* __restrict__ vals, int E) {
    int i = blockIdx.x * blockDim.x + threadIdx.x;
    if (i < E) {
        int r = rows[i];
        int p = atomicAdd(&g_cursor[r], 1);
        g_ecol[p] = cols[i];
        g_eval[p] = vals[i];
    }
}

// ---------------- SpMM1 (+b1, relu): h1 = relu(A @ t1 + b1) -> fp16 ----------
__global__ __launch_bounds__(128) void spmm1_kernel(const float* __restrict__ b1) {
    int r = blockIdx.x;
    int tid = threadIdx.x;
    int s = g_rowptr[r], e = g_rowptr[r + 1];
    float4 acc0 = make_float4(0.f, 0.f, 0.f, 0.f);
    float4 acc1 = make_float4(0.f, 0.f, 0.f, 0.f);
    int i = s;
    for (; i + 1 < e; i += 2) {
        int   c0 = g_ecol[i],     c1 = g_ecol[i + 1];
        float v0 = g_eval[i],     v1 = g_eval[i + 1];
        uint2 r0 = __ldg((const uint2*)(g_t1 + (size_t)c0 * N_HID) + tid);
        uint2 r1 = __ldg((const uint2*)(g_t1 + (size_t)c1 * N_HID) + tid);
        float2 p0 = __half22float2(*(__half2*)&r0.x), p1 = __half22float2(*(__half2*)&r0.y);
        float2 q0 = __half22float2(*(__half2*)&r1.x), q1 = __half22float2(*(__half2*)&r1.y);
        acc0.x += v0 * p0.x; acc0.y += v0 * p0.y; acc0.z += v0 * p1.x; acc0.w += v0 * p1.y;
        acc1.x += v1 * q0.x; acc1.y += v1 * q0.y; acc1.z += v1 * q1.x; acc1.w += v1 * q1.y;
    }
    if (i < e) {
        int   c = g_ecol[i];
        float v = g_eval[i];
        uint2 r0 = __ldg((const uint2*)(g_t1 + (size_t)c * N_HID) + tid);
        float2 p0 = __half22float2(*(__half2*)&r0.x), p1 = __half22float2(*(__half2*)&r0.y);
        acc0.x += v * p0.x; acc0.y += v * p0.y; acc0.z += v * p1.x; acc0.w += v * p1.y;
    }
    float4 bb = ((const float4*)b1)[tid];
    float hx = fmaxf(acc0.x + acc1.x + bb.x, 0.f);
    float hy = fmaxf(acc0.y + acc1.y + bb.y, 0.f);
    float hz = fmaxf(acc0.z + acc1.z + bb.z, 0.f);
    float hw = fmaxf(acc0.w + acc1.w + bb.w, 0.f);
    uint2 o;
    *(__half2*)&o.x = __floats2half2_rn(hx, hy);
    *(__half2*)&o.y = __floats2half2_rn(hz, hw);
    ((uint2*)(g_h1 + (size_t)r * N_HID))[tid] = o;
}

// ---------------- GEMM2: g_t2 = h1_fp16[M,512] @ W2[512,16] ------------------
__global__ __launch_bounds__(256) void gemm2_kernel(const float* __restrict__ W2) {
    __shared__ float Ws[N_HID * N_CLASS];
    for (int i = threadIdx.x; i < N_HID * N_CLASS; i += blockDim.x) Ws[i] = W2[i];
    __syncthreads();
    int row = blockIdx.x * 16 + (threadIdx.x >> 4);
    int c = threadIdx.x & 15;
    if (row >= N_NODES) return;
    const uint2* a4 = (const uint2*)(g_h1 + (size_t)row * N_HID);
    float acc = 0.f;
#pragma unroll 4
    for (int k = 0; k < N_HID / 4; k++) {
        uint2 r = a4[k];
        float2 a0 = __half22float2(*(__half2*)&r.x);
        float2 a1 = __half22float2(*(__half2*)&r.y);
        acc += a0.x * Ws[(4 * k + 0) * N_CLASS + c];
        acc += a0.y * Ws[(4 * k + 1) * N_CLASS + c];
        acc += a1.x * Ws[(4 * k + 2) * N_CLASS + c];
        acc += a1.y * Ws[(4 * k + 3) * N_CLASS + c];
    }
    g_t2[(size_t)row * N_CLASS + c] = acc;
}

// ---------------- SpMM2 (+b2): out = A @ g_t2 + b2 ---------------------------
__global__ void spmm2_kernel(const float* __restrict__ b2, float* __restrict__ out) {
    int w = (blockIdx.x * blockDim.x + threadIdx.x) >> 5;
    int lane = threadIdx.x & 31;
    if (w >= N_NODES) return;
    int s = g_rowptr[w], e = g_rowptr[w + 1];
    float acc = 0.f;
    for (int i = s; i < e; i++) {
        int   c = g_ecol[i];
        float v = g_eval[i];
        if (lane < N_CLASS) acc += v * __ldg(g_t2 + (size_t)c * N_CLASS + lane);
    }
    if (lane < N_CLASS) out[(size_t)w * N_CLASS + lane] = acc + b2[lane];
}

// ---------------- launch: dual-stream DAG ------------------------------------
extern "C" void kernel_launch(void* const* d_in, const int* in_sizes, int n_in,
                              void* d_out, int out_size) {
    const int*   x    = (const int*)d_in[0];
    const int*   rows = (const int*)d_in[1];
    const int*   cols = (const int*)d_in[2];
    const float* vals = (const float*)d_in[3];
    const float* emb  = (const float*)d_in[4];
    const float* W1   = (const float*)d_in[5];
    const float* b1   = (const float*)d_in[6];
    const float* W2   = (const float*)d_in[7];
    const float* b2   = (const float*)d_in[8];
    float* out = (float*)d_out;
    int E = in_sizes[1];

    static cudaStream_t s_side = nullptr;
    static cudaEvent_t  ev_fork = nullptr, ev_w1 = nullptr, ev_join = nullptr;
    if (s_side == nullptr) {
        cudaStreamCreateWithFlags(&s_side, cudaStreamNonBlocking);
        cudaEventCreateWithFlags(&ev_fork, cudaEventDisableTiming);
        cudaEventCreateWithFlags(&ev_w1, cudaEventDisableTiming);
        cudaEventCreateWithFlags(&ev_join, cudaEventDisableTiming);
    }

    cudaFuncSetAttribute(gemm1_mma_kernel,
                         cudaFuncAttributeMaxDynamicSharedMemorySize, GEMM_SMEM);

    // fork: weight-convert + CSR chain on side stream; embed/GEMM on main
    cudaEventRecord(ev_fork, 0);
    cudaStreamWaitEvent(s_side, ev_fork, 0);

    convw1_kernel<<<(N_HID * IN_CH / 2 + 255) / 256, 256, 0, s_side>>>(W1);
    cudaEventRecord(ev_w1, s_side);
    hist_kernel<<<(E + 255) / 256, 256, 0, s_side>>>(rows, E);
    scan_kernel<<<1, 1024, 0, s_side>>>();
    scatter_kernel<<<(E + 255) / 256, 256, 0, s_side>>>(rows, cols, vals, E);
    cudaEventRecord(ev_join, s_side);

    embed_kernel<<<(N_NODES + 1) / 2, 256>>>(x, emb);
    cudaStreamWaitEvent(0, ev_w1, 0);   // gemm1 needs converted W1
    gemm1_mma_kernel<<<dim3(N_HID / 128, M_PAD / 128), 256, GEMM_SMEM>>>();

    cudaStreamWaitEvent(0, ev_join, 0); // sparse kernels need the CSR
    spmm1_kernel<<<N_NODES, 128>>>(b1);
    gemm2_kernel<<<(N_NODES + 15) / 16, 256>>>(W2);
    spmm2_kernel<<<(N_NODES * 32 + 255) / 256, 256>>>(b2, out);
}

// round 17
// speedup vs baseline: 1.3312x; 1.0117x over previous
#include <cuda_runtime.h>
#include <cuda_fp16.h>
#include <cstdint>

#define N_NODES 15279
#define M_PAD   15360
#define E_EDGES 488928
#define IN_CH   1024
#define N_HID   512
#define N_CLASS 16
#define EMB_DIM 128
#define HALF_ROWS 7640                  // spmm1/gemm2 split point

// ---------------- scratch (static device memory; no allocations) -------------
__device__ __half g_a[(size_t)M_PAD * IN_CH];            // 31.5 MB fp16 activations (pad rows stay 0)
__device__ __half g_b[(size_t)N_HID * IN_CH];            // 1 MB  (W1^T fp16)
__device__ __half g_t1[(size_t)N_NODES * N_HID];         // 15.7 MB h0@W1 (fp16)
__device__ __half g_h1[(size_t)N_NODES * N_HID];         // 15.7 MB relu(spmm+b1) (fp16)
__device__ float g_t2[(size_t)N_NODES * N_CLASS];        //  1.0 MB h1@W2
__device__ int   g_counts[N_NODES];                      // zero at load; re-zeroed by scan
__device__ int   g_rowptr[N_NODES + 1];
__device__ int   g_cursor[N_NODES];
__device__ int   g_ecol[E_EDGES];
__device__ float g_eval[E_EDGES];

// ---------------- PTX helpers (sm_80+ features only) -------------------------
static __device__ __forceinline__ uint32_t s2u(const void* p) {
    uint32_t a;
    asm("{ .reg .u64 t; cvta.to.shared.u64 t, %1; cvt.u32.u64 %0, t; }" : "=r"(a) : "l"(p));
    return a;
}
static __device__ __forceinline__ void cp16(uint32_t dst, const void* src) {
    asm volatile("cp.async.cg.shared.global [%0], [%1], 16;" :: "r"(dst), "l"(src));
}
static __device__ __forceinline__ void cp_commit() {
    asm volatile("cp.async.commit_group;" ::: "memory");
}
static __device__ __forceinline__ void cp_wait2() {
    asm volatile("cp.async.wait_group 2;" ::: "memory");
}
static __device__ __forceinline__ void ldsm4(uint32_t* r, uint32_t a) {
    asm volatile("ldmatrix.sync.aligned.m8n8.x4.shared.b16 {%0,%1,%2,%3}, [%4];"
                 : "=r"(r[0]), "=r"(r[1]), "=r"(r[2]), "=r"(r[3]) : "r"(a));
}
static __device__ __forceinline__ void mma16816f16(float* d, const uint32_t* a, const uint32_t* b) {
    asm volatile(
        "mma.sync.aligned.m16n8k16.row.col.f32.f16.f16.f32 "
        "{%0,%1,%2,%3}, {%4,%5,%6,%7}, {%8,%9}, {%0,%1,%2,%3};"
        : "+f"(d[0]), "+f"(d[1]), "+f"(d[2]), "+f"(d[3])
        : "r"(a[0]), "r"(a[1]), "r"(a[2]), "r"(a[3]), "r"(b[0]), "r"(b[1]));
}

// ---------------- embedding lookup + relu -> fp16 (4 nodes/block, MLP=4) -----
// Dtype detection via the GLOBAL first 16 int32 words of x (in-bounds under
// both interpretations): int64 x has all odd (high) words zero; int32 x has
// 8 uniform [0,10000) indices there (all-zero prob ~1e-32).
__global__ void embed_kernel(const int* __restrict__ x32, const float* __restrict__ emb) {
    int g = blockIdx.x;
    int w = threadIdx.x >> 5, lane = threadIdx.x & 31;
    int j = lane & 15;
    int probe = __ldg(x32 + j);
    unsigned nz = __ballot_sync(0xFFFFFFFFu, (j & 1) && probe != 0);
    bool is64 = (nz == 0);
#pragma unroll
    for (int q = 0; q < 2; q++) {
        // process nodes 4g+2q and 4g+2q+1 together (2 gathers in flight x2)
        int n0 = 4 * g + 2 * q, n1 = n0 + 1;
        if (n0 >= N_NODES) return;
        bool v1 = (n1 < N_NODES);
        int idx0 = is64 ? __ldg(x32 + 2 * (n0 * 8 + w)) : __ldg(x32 + n0 * 8 + w);
        int idx1 = 0;
        if (v1) idx1 = is64 ? __ldg(x32 + 2 * (n1 * 8 + w)) : __ldg(x32 + n1 * 8 + w);
        float4 a0 = __ldg((const float4*)(emb + (size_t)idx0 * EMB_DIM) + lane);
        float4 a1 = make_float4(0.f, 0.f, 0.f, 0.f);
        if (v1) a1 = __ldg((const float4*)(emb + (size_t)idx1 * EMB_DIM) + lane);
        __half h0[4], h1[4];
        h0[0] = __float2half(fmaxf(a0.x, 0.f)); h0[1] = __float2half(fmaxf(a0.y, 0.f));
        h0[2] = __float2half(fmaxf(a0.z, 0.f)); h0[3] = __float2half(fmaxf(a0.w, 0.f));
        h1[0] = __float2half(fmaxf(a1.x, 0.f)); h1[1] = __float2half(fmaxf(a1.y, 0.f));
        h1[2] = __float2half(fmaxf(a1.z, 0.f)); h1[3] = __float2half(fmaxf(a1.w, 0.f));
        size_t off0 = (size_t)n0 * IN_CH + w * EMB_DIM + lane * 4;
        *(uint2*)(g_a + off0) = *(uint2*)h0;
        if (v1) {
            size_t off1 = (size_t)n1 * IN_CH + w * EMB_DIM + lane * 4;
            *(uint2*)(g_a + off1) = *(uint2*)h1;
        }
    }
}

// W1 [K=1024, N=512] fp32 -> B [N=512, K=1024] fp16 (transposed)
__global__ void convw1_kernel(const float* __restrict__ W1) {
    int i = blockIdx.x * blockDim.x + threadIdx.x;
    if (i >= N_HID * IN_CH / 2) return;
    int n = i / (IN_CH / 2);
    int k2 = (i % (IN_CH / 2)) * 2;
    float v0 = __ldg(W1 + (size_t)k2 * N_HID + n);
    float v1 = __ldg(W1 + (size_t)(k2 + 1) * N_HID + n);
    __half ph[2] = {__float2half(v0), __float2half(v1)};
    *(uint32_t*)(g_b + (size_t)n * IN_CH + k2) = *(uint32_t*)ph;
}

// ---------------- GEMM1 via mma.sync fp16: t1 = A @ B^T ----------------------
// block tile 128x128, BK=64, 8 warps (4Mx2N), warp tile 32x64,
// SW128-swizzled smem rows (128B), 3-stage cp.async pipeline, 2 CTAs/SM.
#define BKC 64
#define AT  16384                      // 128 rows x 64 fp16 x 2B
#define BT  16384                      // 128 rows x 64 fp16 x 2B
#define SSIZE (AT + BT)                // 32768
#define NSTAGE 3
#define GEMM_SMEM (NSTAGE * SSIZE)     // 98304

static __device__ __forceinline__ void gissue(uint32_t sb, int s, int k0,
                                              int bm, int bn, int tid) {
    if (k0 < IN_CH) {
        uint32_t stage = sb + s * SSIZE;
#pragma unroll
        for (int l = 0; l < 4; l++) {
            int unit = tid + l * 256;
            int r = unit >> 3, u = unit & 7;
            uint32_t bo = (r << 7) | (u << 4);
            uint32_t sw = bo ^ ((bo >> 3) & 0x70);
            cp16(stage + sw, g_a + (size_t)(bm + r) * IN_CH + k0 + u * 8);
            cp16(stage + AT + sw, g_b + (size_t)(bn + r) * IN_CH + k0 + u * 8);
        }
    }
    cp_commit();
}

__global__ void __launch_bounds__(256, 2) gemm1_mma_kernel() {
    extern __shared__ char smem[];
    uint32_t sb = s2u(smem);
    const int tid = threadIdx.x;
    const int wid = tid >> 5, lane = tid & 31;
    const int bm = blockIdx.y * 128, bn = blockIdx.x * 128;
    const int warp_m = (wid & 3) * 32;
    const int warp_n = (wid >> 2) * 64;

    uint32_t a_off[2], b_off[4];
#pragma unroll
    for (int mi = 0; mi < 2; mi++) {
        int row = warp_m + mi * 16 + ((lane >> 3) & 1) * 8 + (lane & 7);
        a_off[mi] = (uint32_t)((row << 7) | ((lane >> 4) << 4));
    }
#pragma unroll
    for (int p = 0; p < 4; p++) {
        int row = warp_n + p * 16 + (lane >> 4) * 8 + (lane & 7);
        b_off[p] = (uint32_t)((row << 7) | (((lane >> 3) & 1) << 4));
    }

    float acc[2][8][4];
#pragma unroll
    for (int mi = 0; mi < 2; mi++)
#pragma unroll
        for (int nj = 0; nj < 8; nj++)
#pragma unroll
            for (int q = 0; q < 4; q++) acc[mi][nj][q] = 0.f;

    gissue(sb, 0, 0, bm, bn, tid);
    gissue(sb, 1, BKC, bm, bn, tid);
    gissue(sb, 2, 2 * BKC, bm, bn, tid);

    const int NCHUNK = IN_CH / BKC;   // 16
    int stage_id = 0;
    for (int c = 0; c < NCHUNK; c++) {
        cp_wait2();
        __syncthreads();
        uint32_t stage = sb + stage_id * SSIZE;
#pragma unroll
        for (int kk = 0; kk < 4; kk++) {
            uint32_t ubase = (uint32_t)(kk * 2) << 4;
            uint32_t af[2][4];
#pragma unroll
            for (int mi = 0; mi < 2; mi++) {
                uint32_t bo = a_off[mi] + ubase;
                ldsm4(af[mi], stage + (bo ^ ((bo >> 3) & 0x70)));
            }
            uint32_t bf[8][2];
#pragma unroll
            for (int p = 0; p < 4; p++) {
                uint32_t bo = b_off[p] + ubase;
                uint32_t t[4];
                ldsm4(t, stage + AT + (bo ^ ((bo >> 3) & 0x70)));
                bf[2 * p][0] = t[0]; bf[2 * p][1] = t[1];
                bf[2 * p + 1][0] = t[2]; bf[2 * p + 1][1] = t[3];
            }
#pragma unroll
            for (int mi = 0; mi < 2; mi++)
#pragma unroll
                for (int nj = 0; nj < 8; nj++)
                    mma16816f16(acc[mi][nj], af[mi], bf[nj]);
        }
        __syncthreads();
        gissue(sb, stage_id, (c + NSTAGE) * BKC, bm, bn, tid);
        stage_id = (stage_id == NSTAGE - 1) ? 0 : stage_id + 1;
    }

    // epilogue -> fp16 t1
#pragma unroll
    for (int mi = 0; mi < 2; mi++) {
        int r0 = bm + warp_m + mi * 16 + (lane >> 2);
        int r1 = r0 + 8;
#pragma unroll
        for (int nj = 0; nj < 8; nj++) {
            int col = bn + warp_n + nj * 8 + (lane & 3) * 2;
            if (r0 < N_NODES)
                *(__half2*)(g_t1 + (size_t)r0 * N_HID + col) =
                    __floats2half2_rn(acc[mi][nj][0], acc[mi][nj][1]);
            if (r1 < N_NODES)
                *(__half2*)(g_t1 + (size_t)r1 * N_HID + col) =
                    __floats2half2_rn(acc[mi][nj][2], acc[mi][nj][3]);
        }
    }
}

// ---------------- CSR build --------------------------------------------------
__global__ void hist_kernel(const int* __restrict__ rows, int E) {
    int i = blockIdx.x * blockDim.x + threadIdx.x;
    if (i < E) atomicAdd(&g_counts[rows[i]], 1);
}

// thread-coarsened shuffle scan; zeroes g_counts and seeds g_cursor
#define SCAN_PER 15
__global__ void __launch_bounds__(1024) scan_kernel() {
    __shared__ int wsum[32];
    int tid = threadIdx.x;
    int lane = tid & 31, w = tid >> 5;
    int base = tid * SCAN_PER;
    int c[SCAN_PER];
    int sum = 0;
#pragma unroll
    for (int i = 0; i < SCAN_PER; i++) {
        int g = base + i;
        c[i] = (g < N_NODES) ? g_counts[g] : 0;
        if (g < N_NODES) g_counts[g] = 0;
        sum += c[i];
    }
    int incl = sum;
#pragma unroll
    for (int off = 1; off < 32; off <<= 1) {
        int t = __shfl_up_sync(0xFFFFFFFFu, incl, off);
        if (lane >= off) incl += t;
    }
    if (lane == 31) wsum[w] = incl;
    __syncthreads();
    if (w == 0) {
        int v = wsum[lane];
#pragma unroll
        for (int off = 1; off < 32; off <<= 1) {
            int t = __shfl_up_sync(0xFFFFFFFFu, v, off);
            if (lane >= off) v += t;
        }
        wsum[lane] = v;
    }
    __syncthreads();
    int run = (w > 0 ? wsum[w - 1] : 0) + incl - sum;   // exclusive prefix
    if (tid == 0) g_rowptr[0] = 0;
#pragma unroll
    for (int i = 0; i < SCAN_PER; i++) {
        int g = base + i;
        if (g < N_NODES) {
            g_cursor[g] = run;
            run += c[i];
            g_rowptr[g + 1] = run;
        }
    }
}

__global__ void scatter_kernel(const int* __restrict__ rows, const int* __restrict__ cols,
                               const float* __restrict__ vals, int E) {
    int i = blockIdx.x * blockDim.x + threadIdx.x;
    if (i < E) {
        int r = rows[i];
        int p = atomicAdd(&g_cursor[r], 1);
        g_ecol[p] = cols[i];
        g_eval[p] = vals[i];
    }
}

// ---------------- SpMM1 (+b1, relu): h1 = relu(A @ t1 + b1) -> fp16 ----------
// one 128-thread block per row; row_base selects the row range (split launch)
__global__ __launch_bounds__(128) void spmm1_kernel(const float* __restrict__ b1, int row_base) {
    int r = row_base + blockIdx.x;
    int tid = threadIdx.x;
    int s = g_rowptr[r], e = g_rowptr[r + 1];
    float4 acc0 = make_float4(0.f, 0.f, 0.f, 0.f);
    float4 acc1 = make_float4(0.f, 0.f, 0.f, 0.f);
    int i = s;
    for (; i + 1 < e; i += 2) {
        int   c0 = g_ecol[i],     c1 = g_ecol[i + 1];
        float v0 = g_eval[i],     v1 = g_eval[i + 1];
        uint2 r0 = __ldg((const uint2*)(g_t1 + (size_t)c0 * N_HID) + tid);
        uint2 r1 = __ldg((const uint2*)(g_t1 + (size_t)c1 * N_HID) + tid);
        float2 p0 = __half22float2(*(__half2*)&r0.x), p1 = __half22float2(*(__half2*)&r0.y);
        float2 q0 = __half22float2(*(__half2*)&r1.x), q1 = __half22float2(*(__half2*)&r1.y);
        acc0.x += v0 * p0.x; acc0.y += v0 * p0.y; acc0.z += v0 * p1.x; acc0.w += v0 * p1.y;
        acc1.x += v1 * q0.x; acc1.y += v1 * q0.y; acc1.z += v1 * q1.x; acc1.w += v1 * q1.y;
    }
    if (i < e) {
        int   c = g_ecol[i];
        float v = g_eval[i];
        uint2 r0 = __ldg((const uint2*)(g_t1 + (size_t)c * N_HID) + tid);
        float2 p0 = __half22float2(*(__half2*)&r0.x), p1 = __half22float2(*(__half2*)&r0.y);
        acc0.x += v * p0.x; acc0.y += v * p0.y; acc0.z += v * p1.x; acc0.w += v * p1.y;
    }
    float4 bb = ((const float4*)b1)[tid];
    float hx = fmaxf(acc0.x + acc1.x + bb.x, 0.f);
    float hy = fmaxf(acc0.y + acc1.y + bb.y, 0.f);
    float hz = fmaxf(acc0.z + acc1.z + bb.z, 0.f);
    float hw = fmaxf(acc0.w + acc1.w + bb.w, 0.f);
    uint2 o;
    *(__half2*)&o.x = __floats2half2_rn(hx, hy);
    *(__half2*)&o.y = __floats2half2_rn(hz, hw);
    ((uint2*)(g_h1 + (size_t)r * N_HID))[tid] = o;
}

// ---------------- GEMM2: g_t2 = h1_fp16[M,512] @ W2[512,16] (row range) ------
__global__ __launch_bounds__(256) void gemm2_kernel(const float* __restrict__ W2,
                                                    int row_base, int row_count) {
    __shared__ float Ws[N_HID * N_CLASS];
    for (int i = threadIdx.x; i < N_HID * N_CLASS; i += blockDim.x) Ws[i] = W2[i];
    __syncthreads();
    int local = blockIdx.x * 16 + (threadIdx.x >> 4);
    int c = threadIdx.x & 15;
    if (local >= row_count) return;
    int row = row_base + local;
    const uint2* a4 = (const uint2*)(g_h1 + (size_t)row * N_HID);
    float acc = 0.f;
#pragma unroll 4
    for (int k = 0; k < N_HID / 4; k++) {
        uint2 r = a4[k];
        float2 a0 = __half22float2(*(__half2*)&r.x);
        float2 a1 = __half22float2(*(__half2*)&r.y);
        acc += a0.x * Ws[(4 * k + 0) * N_CLASS + c];
        acc += a0.y * Ws[(4 * k + 1) * N_CLASS + c];
        acc += a1.x * Ws[(4 * k + 2) * N_CLASS + c];
        acc += a1.y * Ws[(4 * k + 3) * N_CLASS + c];
    }
    g_t2[(size_t)row * N_CLASS + c] = acc;
}

// ---------------- SpMM2 (+b2): out = A @ g_t2 + b2 (2-way unrolled) ----------
__global__ void spmm2_kernel(const float* __restrict__ b2, float* __restrict__ out) {
    int w = (blockIdx.x * blockDim.x + threadIdx.x) >> 5;
    int lane = threadIdx.x & 31;
    if (w >= N_NODES) return;
    int s = g_rowptr[w], e = g_rowptr[w + 1];
    float acc0 = 0.f, acc1 = 0.f;
    int i = s;
    for (; i + 1 < e; i += 2) {
        int   c0 = g_ecol[i],   c1 = g_ecol[i + 1];
        float v0 = g_eval[i],   v1 = g_eval[i + 1];
        if (lane < N_CLASS) {
            float t0 = __ldg(g_t2 + (size_t)c0 * N_CLASS + lane);
            float t1 = __ldg(g_t2 + (size_t)c1 * N_CLASS + lane);
            acc0 += v0 * t0;
            acc1 += v1 * t1;
        }
    }
    if (i < e) {
        int   c = g_ecol[i];
        float v = g_eval[i];
        if (lane < N_CLASS) acc0 += v * __ldg(g_t2 + (size_t)c * N_CLASS + lane);
    }
    if (lane < N_CLASS) out[(size_t)w * N_CLASS + lane] = acc0 + acc1 + b2[lane];
}

// ---------------- launch: dual-stream DAG with gemm2 overlap ------------------
extern "C" void kernel_launch(void* const* d_in, const int* in_sizes, int n_in,
                              void* d_out, int out_size) {
    const int*   x    = (const int*)d_in[0];
    const int*   rows = (const int*)d_in[1];
    const int*   cols = (const int*)d_in[2];
    const float* vals = (const float*)d_in[3];
    const float* emb  = (const float*)d_in[4];
    const float* W1   = (const float*)d_in[5];
    const float* b1   = (const float*)d_in[6];
    const float* W2   = (const float*)d_in[7];
    const float* b2   = (const float*)d_in[8];
    float* out = (float*)d_out;
    int E = in_sizes[1];

    static cudaStream_t s_side = nullptr;
    static cudaEvent_t  ev_fork = nullptr, ev_w1 = nullptr, ev_join = nullptr;
    static cudaEvent_t  ev_s1a = nullptr, ev_g2a = nullptr;
    if (s_side == nullptr) {
        cudaStreamCreateWithFlags(&s_side, cudaStreamNonBlocking);
        cudaEventCreateWithFlags(&ev_fork, cudaEventDisableTiming);
        cudaEventCreateWithFlags(&ev_w1, cudaEventDisableTiming);
        cudaEventCreateWithFlags(&ev_join, cudaEventDisableTiming);
        cudaEventCreateWithFlags(&ev_s1a, cudaEventDisableTiming);
        cudaEventCreateWithFlags(&ev_g2a, cudaEventDisableTiming);
    }

    cudaFuncSetAttribute(gemm1_mma_kernel,
                         cudaFuncAttributeMaxDynamicSharedMemorySize, GEMM_SMEM);

    // fork: weight-convert + CSR chain on side stream; embed/GEMM on main
    cudaEventRecord(ev_fork, 0);
    cudaStreamWaitEvent(s_side, ev_fork, 0);

    convw1_kernel<<<(N_HID * IN_CH / 2 + 255) / 256, 256, 0, s_side>>>(W1);
    cudaEventRecord(ev_w1, s_side);
    hist_kernel<<<(E + 255) / 256, 256, 0, s_side>>>(rows, E);
    scan_kernel<<<1, 1024, 0, s_side>>>();
    scatter_kernel<<<(E + 255) / 256, 256, 0, s_side>>>(rows, cols, vals, E);
    cudaEventRecord(ev_join, s_side);

    embed_kernel<<<(N_NODES + 3) / 4, 256>>>(x, emb);
    cudaStreamWaitEvent(0, ev_w1, 0);   // gemm1 needs converted W1
    gemm1_mma_kernel<<<dim3(N_HID / 128, M_PAD / 128), 256, GEMM_SMEM>>>();

    cudaStreamWaitEvent(0, ev_join, 0); // sparse kernels need the CSR

    // spmm1 half 0 -> (side) gemm2 half 0 overlapping spmm1 half 1
    spmm1_kernel<<<HALF_ROWS, 128>>>(b1, 0);
    cudaEventRecord(ev_s1a, 0);
    cudaStreamWaitEvent(s_side, ev_s1a, 0);
    gemm2_kernel<<<(HALF_ROWS + 15) / 16, 256, 0, s_side>>>(W2, 0, HALF_ROWS);
    cudaEventRecord(ev_g2a, s_side);

    spmm1_kernel<<<N_NODES - HALF_ROWS, 128>>>(b1, HALF_ROWS);
    gemm2_kernel<<<(N_NODES - HALF_ROWS + 15) / 16, 256>>>(W2, HALF_ROWS, N_NODES - HALF_ROWS);

    cudaStreamWaitEvent(0, ev_g2a, 0);  // spmm2 needs both gemm2 halves
    spmm2_kernel<<<(N_NODES * 32 + 255) / 256, 256>>>(b2, out);
}